// round 3
// baseline (speedup 1.0000x reference)
#include <cuda_runtime.h>
#include <math.h>

#define NSCALES 128
#define LSIG    8192
#define NBATCH  32
#define PRECN   1024
#define TN      1024          // outputs per block
#define RPT     8             // outputs per thread (consecutive)
#define NTHREADS (TN / RPT)   // 128
#define MAXKF   2049          // 16*128 + 1 (longest filter)
#define MAXKFP  2064          // padded to multiple of 16
#define WMAX    (TN + MAXKFP + 32)   // 3120 floats

__device__ double g_int_psi[PRECN];
__device__ float  g_filt[NSCALES][MAXKFP];

// Step 1: int_psi = cumsum(psi)*step with numpy-exact linspace sampling.
// numpy linspace(-8,8,1024): x[i] = fl(i*(16/1023)) + (-8), x[1023] = 8.
// step = x[1] - x[0] = fl(fl(16/1023 - 8) + 8)  (NOT 16/1023 exactly!)
__global__ void psi_kernel() {
    __shared__ double sp[PRECN];
    int t = threadIdx.x;
    const double st0  = 16.0 / 1023.0;
    const double step = __dadd_rn(__dadd_rn(st0, -8.0), 8.0);
    double xv = (t == PRECN - 1) ? 8.0
                                 : __dadd_rn(__dmul_rn((double)t, st0), -8.0);
    double psi = 0.5641895835477563 /* pi^-0.5 */
               * exp(-__dmul_rn(xv, xv))
               * cos(__dmul_rn(6.283185307179586, xv));
    sp[t] = psi;
    __syncthreads();
    // Hillis-Steele inclusive scan (double); order differences ~1e-13,
    // invisible after the float32 cast downstream.
    for (int off = 1; off < PRECN; off <<= 1) {
        double v = (t >= off) ? sp[t - off] : 0.0;
        __syncthreads();
        sp[t] += v;
        __syncthreads();
    }
    g_int_psi[t] = __dmul_rn(sp[t], step);
}

// Step 2: full resampled filter per scale (reference filts row, float32):
// F[k] = f32(int_psi[floor(k / (s*step))]) for k in [0, 16s], zero-padded.
// floor must bit-match numpy: exact same step, rn mul/div, no FMA contraction.
__global__ void filt_kernel() {
    int i = blockIdx.x;          // scale index
    int s = i + 1;
    const double st0  = 16.0 / 1023.0;
    const double step = __dadd_rn(__dadd_rn(st0, -8.0), 8.0);
    const double sstep = __dmul_rn((double)s, step);
    int Kf = 16 * s + 1;
    for (int k = threadIdx.x; k < MAXKFP; k += blockDim.x) {
        float v = 0.f;
        if (k < Kf) {
            int idx = (int)floor(__ddiv_rn((double)k, sstep));
            if (idx > PRECN - 1) idx = PRECN - 1;
            if (idx < 0) idx = 0;
            v = (float)g_int_psi[idx];
        }
        g_filt[i][k] = v;
    }
}

// Step 3: replicate reference numerics: C[n] = sum_j F[j]*x[n-8s+j] in fp32,
// out[n] = -sqrt(s) * (C[n+1] - C[n]).
// Thread computes 9 C values (outputs m0..m0+7 need C[m0..m0+8]) via a
// 16-wide register ring refilled with float4 SMEM loads (conflict-light).
__global__ __launch_bounds__(NTHREADS) void cwt_kernel(
    const float* __restrict__ x, float* __restrict__ out)
{
    __shared__ float xs[WMAX];
    __shared__ float Fs[MAXKFP];

    const int tile = blockIdx.x;
    const int i    = blockIdx.y;
    const int b    = blockIdx.z;
    const int s    = i + 1;
    const int Kf   = 16 * s + 1;
    const int Kfp  = (Kf + 15) & ~15;
    const int n0   = tile * TN;
    const int a0   = n0 - 8 * s;          // global x index of xs[0]

    const float* xb = x + (size_t)b * LSIG;
    // zero-fill the whole window (ring reads past Kf; garbage could be NaN)
    for (int p = threadIdx.x; p < WMAX; p += NTHREADS) {
        int g = a0 + p;
        xs[p] = (g >= 0 && g < LSIG) ? xb[g] : 0.f;
    }
    for (int j = threadIdx.x; j < Kfp; j += NTHREADS)
        Fs[j] = g_filt[i][j];
    __syncthreads();

    const int m0 = threadIdx.x * RPT;
    float acc[RPT + 1];
    float ring[16];
#pragma unroll
    for (int c = 0; c <= RPT; c++) acc[c] = 0.f;
#pragma unroll
    for (int k = 0; k < 16; k++) ring[k] = xs[m0 + k];

    for (int j = 0; j < Kfp; j += 16) {
        float4 ta = *(const float4*)&Fs[j];
        float4 tb = *(const float4*)&Fs[j + 4];
        float tv0[8] = {ta.x, ta.y, ta.z, ta.w, tb.x, tb.y, tb.z, tb.w};
#pragma unroll
        for (int u = 0; u < 8; u++)
#pragma unroll
            for (int c = 0; c <= RPT; c++)
                acc[c] = fmaf(tv0[u], ring[u + c], acc[c]);

        // refill lower half: xs[m0+j+16 .. m0+j+23]
        {
            float4 na = *(const float4*)&xs[m0 + j + 16];
            float4 nb = *(const float4*)&xs[m0 + j + 20];
            ring[0] = na.x; ring[1] = na.y; ring[2] = na.z; ring[3] = na.w;
            ring[4] = nb.x; ring[5] = nb.y; ring[6] = nb.z; ring[7] = nb.w;
        }

        float4 tc = *(const float4*)&Fs[j + 8];
        float4 td = *(const float4*)&Fs[j + 12];
        float tv1[8] = {tc.x, tc.y, tc.z, tc.w, td.x, td.y, td.z, td.w};
#pragma unroll
        for (int u = 0; u < 8; u++)
#pragma unroll
            for (int c = 0; c <= RPT; c++)
                acc[c] = fmaf(tv1[u], ring[(8 + u + c) & 15], acc[c]);

        // refill upper half: xs[m0+j+24 .. m0+j+31]
        {
            float4 nc4 = *(const float4*)&xs[m0 + j + 24];
            float4 nd4 = *(const float4*)&xs[m0 + j + 28];
            ring[8]  = nc4.x; ring[9]  = nc4.y; ring[10] = nc4.z; ring[11] = nc4.w;
            ring[12] = nd4.x; ring[13] = nd4.y; ring[14] = nd4.z; ring[15] = nd4.w;
        }
    }

    const float sq = sqrtf((float)s);
    float o[RPT];
#pragma unroll
    for (int c = 0; c < RPT; c++)
        o[c] = -sq * (acc[c + 1] - acc[c]);

    float* op = out + ((size_t)(b * NSCALES + i)) * LSIG + n0 + m0;
    float4* o4 = reinterpret_cast<float4*>(op);
    o4[0] = make_float4(o[0], o[1], o[2], o[3]);
    o4[1] = make_float4(o[4], o[5], o[6], o[7]);
}

extern "C" void kernel_launch(void* const* d_in, const int* in_sizes, int n_in,
                              void* d_out, int out_size)
{
    const float* x = (const float*)d_in[0];
    float* out = (float*)d_out;

    psi_kernel<<<1, PRECN>>>();
    filt_kernel<<<NSCALES, 256>>>();

    dim3 grid(LSIG / TN, NSCALES, NBATCH);
    cwt_kernel<<<grid, NTHREADS>>>(x, out);
}